// round 10
// baseline (speedup 1.0000x reference)
#include <cuda_runtime.h>
#include <cuda_bf16.h>
#include <math.h>

// ---------------------------------------------------------------------------
// SlatewiseGRU via tensor cores: mma.sync m16n8k16 bf16, 3-term split
// (hi*hi + hi*lo + lo*hi), fp32 accumulate.
// R9 = R8 + fix: barrier between the pre-loop x-side MMA (reads x buf0) and
// the first loop iteration's staging write of x_2 into the same buffer.
// One barrier per steady-state step. h ping-pongs between two SMEM buffers;
// staging writes x(t+2); out-reduction of t-1 fills the acc-drain window;
// epilogue interleaved with x-side MMA of t+1 per m-tile.
// ---------------------------------------------------------------------------

#define DD   128
#define LL   32
#define NSEQ 8192
#define TN   32
#define NTHR 256
#define NCTA (NSEQ / TN)   // 256
#define SMP  136           // padded SMEM row stride (bf16 elems); row = 272 B

// Packed B-fragments: [wt:4 (ih_hi,ih_lo,hh_hi,hh_lo)][kt:8][ntile:48][lane:32]
__device__ uint2 g_wpack[4 * 8 * 48 * 32];

__global__ void prep_weights(const float* __restrict__ W_ih,
                             const float* __restrict__ W_hh) {
    int idx = blockIdx.x * blockDim.x + threadIdx.x;
    if (idx >= 4 * 8 * 48 * 32) return;
    int l  = idx & 31;
    int r  = idx >> 5;
    int nt = r % 48; r /= 48;
    int kt = r % 8;  r /= 8;
    int wt = r;
    const float* W = (wt < 2) ? W_ih : W_hh;
    bool lo = (wt & 1);
    int gg = nt / 16, w = nt % 16;
    int j  = gg * 128 + w * 8 + (l >> 2);
    int d0 = kt * 16 + (l & 3) * 2;
    unsigned short e[4];
    #pragma unroll
    for (int q = 0; q < 4; ++q) {
        int d = d0 + (q & 1) + (q >> 1) * 8;
        float f = W[j * DD + d];
        __nv_bfloat16 h = __float2bfloat16(f);
        if (lo) h = __float2bfloat16(f - __bfloat162float(h));
        e[q] = __bfloat16_as_ushort(h);
    }
    uint2 v;
    v.x = (unsigned)e[0] | ((unsigned)e[1] << 16);
    v.y = (unsigned)e[2] | ((unsigned)e[3] << 16);
    g_wpack[idx] = v;
}

__device__ __forceinline__ unsigned pk(__nv_bfloat16 a, __nv_bfloat16 b) {
    return (unsigned)__bfloat16_as_ushort(a) | ((unsigned)__bfloat16_as_ushort(b) << 16);
}
__device__ __forceinline__ float bflo(unsigned u) {
    return __bfloat162float(__ushort_as_bfloat16((unsigned short)(u & 0xffffu)));
}
__device__ __forceinline__ float bfhi(unsigned u) {
    return __bfloat162float(__ushort_as_bfloat16((unsigned short)(u >> 16)));
}

__device__ __forceinline__ void mma16816(float* c, const unsigned* a, uint2 b) {
    asm volatile(
        "mma.sync.aligned.m16n8k16.row.col.f32.bf16.bf16.f32 "
        "{%0,%1,%2,%3}, {%4,%5,%6,%7}, {%8,%9}, {%0,%1,%2,%3};\n"
        : "+f"(c[0]), "+f"(c[1]), "+f"(c[2]), "+f"(c[3])
        : "r"(a[0]), "r"(a[1]), "r"(a[2]), "r"(a[3]), "r"(b.x), "r"(b.y));
}

__device__ __forceinline__ void ldsm4(unsigned* r, unsigned addr) {
    asm volatile("ldmatrix.sync.aligned.m8n8.x4.shared.b16 {%0,%1,%2,%3}, [%4];"
                 : "=r"(r[0]), "=r"(r[1]), "=r"(r[2]), "=r"(r[3]) : "r"(addr));
}

__device__ __forceinline__ float sigm(float x) {
    return __fdividef(1.f, 1.f + __expf(-x));
}
__device__ __forceinline__ float tanhfast(float x) {
    return 1.f - __fdividef(2.f, __expf(2.f * x) + 1.f);
}

// x-side MMA for one m-tile: 8 kt, 18 HMMA each (hi*Bh, hi*Bl, lo*Bh).
__device__ __forceinline__ void xside_mt(float acc[4][2][2][4], int mt,
                                         unsigned xA_h, unsigned xA_l,
                                         int w, int l) {
    #pragma unroll
    for (int kt = 0; kt < 8; ++kt) {
        uint2 Bh[3][2], Bl[3][2];
        #pragma unroll
        for (int gg = 0; gg < 3; ++gg)
            #pragma unroll
            for (int nt = 0; nt < 2; ++nt) {
                int off = (gg * 16 + 2 * w + nt) * 32 + l;
                Bh[gg][nt] = g_wpack[(0 * 8 + kt) * 1536 + off];
                Bl[gg][nt] = g_wpack[(1 * 8 + kt) * 1536 + off];
            }
        unsigned a[4];
        ldsm4(a, xA_h + mt * (16 * SMP * 2) + kt * 32);
        #pragma unroll
        for (int gg = 0; gg < 3; ++gg) {
            const int s = (gg < 2) ? gg : 2;
            #pragma unroll
            for (int nt = 0; nt < 2; ++nt) {
                mma16816(acc[s][mt][nt], a, Bh[gg][nt]);
                mma16816(acc[s][mt][nt], a, Bl[gg][nt]);
            }
        }
        ldsm4(a, xA_l + mt * (16 * SMP * 2) + kt * 32);
        #pragma unroll
        for (int gg = 0; gg < 3; ++gg) {
            const int s = (gg < 2) ? gg : 2;
            #pragma unroll
            for (int nt = 0; nt < 2; ++nt)
                mma16816(acc[s][mt][nt], a, Bh[gg][nt]);
        }
    }
}

extern __shared__ char smraw[];

__global__ void __launch_bounds__(NTHR, 2)
gru_mma(const float* __restrict__ item,   // [N, L, D]
        const float* __restrict__ user,   // [N, D]
        const float* __restrict__ b_ih,   // [384]
        const float* __restrict__ b_hh,   // [384]
        const float* __restrict__ W_out,  // [128]
        const float* __restrict__ b_out,  // [1]
        float* __restrict__ out)          // [N, L]
{
    // SMEM map: x hi[2] | x lo[2] | h hi[2] | h lo[2] | outb[2][8*TN] | biases
    unsigned short* xbh = (unsigned short*)smraw;        // [2][TN*SMP]
    unsigned short* xbl = xbh + 2 * TN * SMP;            // [2][TN*SMP]
    unsigned short* hbh = xbl + 2 * TN * SMP;            // [2][TN*SMP]
    unsigned short* hbl = hbh + 2 * TN * SMP;            // [2][TN*SMP]
    float* outb = (float*)(hbl + 2 * TN * SMP);          // [2][8*TN]
    float* Bs   = outb + 2 * 8 * TN;                     // [512]

    const int tid = threadIdx.x;
    const int w   = tid >> 5;   // 8 warps
    const int l   = tid & 31;
    const int g   = l >> 2;
    const int tg  = l & 3;
    const int nBase = blockIdx.x * TN;

    // Biases -> SMEM: [0:256) r,z combined; [256:384) b_ih n; [384:512) b_hh n.
    for (int i = tid; i < 512; i += NTHR) {
        float v;
        if (i < 256)      v = b_ih[i] + b_hh[i];
        else if (i < 384) v = b_ih[i];
        else              v = b_hh[i - 128];
        Bs[i] = v;
    }

    // ldmatrix per-thread base addresses
    const int rowsel = l & 15;
    const int halfc  = l >> 4;
    const unsigned lmOff = (unsigned)((rowsel * SMP + halfc * 8) * 2);
    unsigned xhA[2], xlA[2], hhA[2], hlA[2];
    xhA[0] = (unsigned)__cvta_generic_to_shared(xbh) + lmOff;
    xhA[1] = xhA[0] + TN * SMP * 2;
    xlA[0] = (unsigned)__cvta_generic_to_shared(xbl) + lmOff;
    xlA[1] = xlA[0] + TN * SMP * 2;
    hhA[0] = (unsigned)__cvta_generic_to_shared(hbh) + lmOff;
    hhA[1] = hhA[0] + TN * SMP * 2;
    hlA[0] = (unsigned)__cvta_generic_to_shared(hbl) + lmOff;
    hlA[1] = hlA[0] + TN * SMP * 2;

    const int ua = w * 16 + tg * 2;       // nt = 0
    const int ub = ua + 8;                // nt = 1
    float2 woA = *(const float2*)(W_out + ua);
    float2 woB = *(const float2*)(W_out + ub);
    const float bo = b_out[0];

    // h0 = user_embs into h buffer 0 (hi/lo split), owner-thread init.
    #pragma unroll
    for (int mt = 0; mt < 2; ++mt)
        #pragma unroll
        for (int rh = 0; rh < 2; ++rh) {
            int row = mt * 16 + g + rh * 8;
            #pragma unroll
            for (int nt = 0; nt < 2; ++nt) {
                int u = (nt ? ub : ua);
                float2 v = *(const float2*)(user + (size_t)(nBase + row) * DD + u);
                __nv_bfloat16 a0 = __float2bfloat16(v.x);
                __nv_bfloat16 a1 = __float2bfloat16(v.y);
                *(unsigned*)&hbh[row * SMP + u] = pk(a0, a1);
                *(unsigned*)&hbl[row * SMP + u] =
                    pk(__float2bfloat16(v.x - __bfloat162float(a0)),
                       __float2bfloat16(v.y - __bfloat162float(a1)));
            }
        }

    // staging coordinates (4 float4 per thread per step)
    int srow[4], scol[4];
    #pragma unroll
    for (int ii = 0; ii < 4; ++ii) {
        int i = tid + ii * NTHR;
        srow[ii] = i >> 5;
        scol[ii] = (i & 31) * 4;
    }

    // ---- prologue: stage x_0 -> buf0, x_1 -> buf1, prefetch x_2 ----
    float4 xr[4];
    #pragma unroll
    for (int tt = 0; tt < 2; ++tt) {
        #pragma unroll
        for (int ii = 0; ii < 4; ++ii)
            xr[ii] = *(const float4*)(item +
                       ((size_t)(nBase + srow[ii]) * LL + tt) * DD + scol[ii]);
        #pragma unroll
        for (int ii = 0; ii < 4; ++ii) {
            float4 v = xr[ii];
            __nv_bfloat16 h0 = __float2bfloat16(v.x), h1 = __float2bfloat16(v.y);
            __nv_bfloat16 h2 = __float2bfloat16(v.z), h3 = __float2bfloat16(v.w);
            uint2 hv, lv;
            hv.x = pk(h0, h1); hv.y = pk(h2, h3);
            lv.x = pk(__float2bfloat16(v.x - __bfloat162float(h0)),
                      __float2bfloat16(v.y - __bfloat162float(h1)));
            lv.y = pk(__float2bfloat16(v.z - __bfloat162float(h2)),
                      __float2bfloat16(v.w - __bfloat162float(h3)));
            *(uint2*)&xbh[tt * TN * SMP + srow[ii] * SMP + scol[ii]] = hv;
            *(uint2*)&xbl[tt * TN * SMP + srow[ii] * SMP + scol[ii]] = lv;
        }
    }
    #pragma unroll
    for (int ii = 0; ii < 4; ++ii)
        xr[ii] = *(const float4*)(item +
                   ((size_t)(nBase + srow[ii]) * LL + 2) * DD + scol[ii]);
    __syncthreads();   // x0, x1, h0, biases visible

    float acc[4][2][2][4];
    #pragma unroll
    for (int s = 0; s < 4; ++s)
        #pragma unroll
        for (int mt = 0; mt < 2; ++mt)
            #pragma unroll
            for (int nt = 0; nt < 2; ++nt)
                #pragma unroll
                for (int q = 0; q < 4; ++q) acc[s][mt][nt][q] = 0.f;

    // x-side MMA for t=0 from buffer 0
    xside_mt(acc, 0, xhA[0], xlA[0], w, l);
    xside_mt(acc, 1, xhA[0], xlA[0], w, l);
    __syncthreads();   // FIX: all warps' reads of x buf0 (x_0) must complete
                       // before t=0 stages x_2 into the same buffer.

    for (int t = 0; t < LL; ++t) {
        const int p = t & 1;        // h read buffer; write goes to 1-p
        const int xn = (t + 1) & 1; // x buffer for step t+1

        // ---- stage x_{t+2} from xr (writes xbuf[t&1], read after barrier) ----
        if (t <= LL - 3) {
            #pragma unroll
            for (int ii = 0; ii < 4; ++ii) {
                float4 v = xr[ii];
                __nv_bfloat16 h0 = __float2bfloat16(v.x), h1 = __float2bfloat16(v.y);
                __nv_bfloat16 h2 = __float2bfloat16(v.z), h3 = __float2bfloat16(v.w);
                uint2 hv, lv;
                hv.x = pk(h0, h1); hv.y = pk(h2, h3);
                lv.x = pk(__float2bfloat16(v.x - __bfloat162float(h0)),
                          __float2bfloat16(v.y - __bfloat162float(h1)));
                lv.y = pk(__float2bfloat16(v.z - __bfloat162float(h2)),
                          __float2bfloat16(v.w - __bfloat162float(h3)));
                *(uint2*)&xbh[p * TN * SMP + srow[ii] * SMP + scol[ii]] = hv;
                *(uint2*)&xbl[p * TN * SMP + srow[ii] * SMP + scol[ii]] = lv;
            }
        }
        // ---- prefetch x_{t+3} early: latency hides under the whole step ----
        if (t <= LL - 4) {
            #pragma unroll
            for (int ii = 0; ii < 4; ++ii)
                xr[ii] = *(const float4*)(item +
                           ((size_t)(nBase + srow[ii]) * LL + (t + 3)) * DD + scol[ii]);
        }

        // ---- h-side MMA(t): reads hbuf[p] ----
        #pragma unroll
        for (int kt = 0; kt < 8; ++kt) {
            uint2 Bh[3][2], Bl[3][2];
            #pragma unroll
            for (int gg = 0; gg < 3; ++gg)
                #pragma unroll
                for (int nt = 0; nt < 2; ++nt) {
                    int off = (gg * 16 + 2 * w + nt) * 32 + l;
                    Bh[gg][nt] = g_wpack[(2 * 8 + kt) * 1536 + off];
                    Bl[gg][nt] = g_wpack[(3 * 8 + kt) * 1536 + off];
                }
            unsigned a[2][4];
            #pragma unroll
            for (int mt = 0; mt < 2; ++mt)
                ldsm4(a[mt], hhA[p] + mt * (16 * SMP * 2) + kt * 32);
            #pragma unroll
            for (int gg = 0; gg < 3; ++gg) {
                const int s = (gg < 2) ? gg : 3;
                #pragma unroll
                for (int nt = 0; nt < 2; ++nt)
                    #pragma unroll
                    for (int mt = 0; mt < 2; ++mt) {
                        mma16816(acc[s][mt][nt], a[mt], Bh[gg][nt]);
                        mma16816(acc[s][mt][nt], a[mt], Bl[gg][nt]);
                    }
            }
            #pragma unroll
            for (int mt = 0; mt < 2; ++mt)
                ldsm4(a[mt], hlA[p] + mt * (16 * SMP * 2) + kt * 32);
            #pragma unroll
            for (int gg = 0; gg < 3; ++gg) {
                const int s = (gg < 2) ? gg : 3;
                #pragma unroll
                for (int nt = 0; nt < 2; ++nt)
                    #pragma unroll
                    for (int mt = 0; mt < 2; ++mt)
                        mma16816(acc[s][mt][nt], a[mt], Bh[gg][nt]);
            }
        }

        // ---- output reduction for step t-1 (fills the acc-drain window) ----
        if (t > 0 && tid < TN) {
            float s = bo;
            #pragma unroll
            for (int ww = 0; ww < 8; ++ww)
                s += outb[((t - 1) & 1) * 8 * TN + ww * TN + tid];
            out[(size_t)(nBase + tid) * LL + (t - 1)] = s;
        }

        // ---- epilogue(t) per m-tile, interleaved with x-side MMA(t+1) ----
        #pragma unroll
        for (int mt = 0; mt < 2; ++mt) {
            #pragma unroll
            for (int rh = 0; rh < 2; ++rh) {
                int row = mt * 16 + g + rh * 8;
                float pr = 0.f;
                #pragma unroll
                for (int nt = 0; nt < 2; ++nt) {
                    int u = (nt ? ub : ua);
                    float wox = nt ? woB.x : woA.x;
                    float woy = nt ? woB.y : woA.y;
                    float r0 = sigm(acc[0][mt][nt][rh * 2]     + Bs[u]);
                    float r1 = sigm(acc[0][mt][nt][rh * 2 + 1] + Bs[u + 1]);
                    float z0 = sigm(acc[1][mt][nt][rh * 2]     + Bs[128 + u]);
                    float z1 = sigm(acc[1][mt][nt][rh * 2 + 1] + Bs[128 + u + 1]);
                    float n0 = tanhfast(acc[2][mt][nt][rh * 2] + Bs[256 + u]
                               + r0 * (acc[3][mt][nt][rh * 2]  + Bs[384 + u]));
                    float n1 = tanhfast(acc[2][mt][nt][rh * 2 + 1] + Bs[256 + u + 1]
                               + r1 * (acc[3][mt][nt][rh * 2 + 1]  + Bs[384 + u + 1]));
                    // h_old from the stable read buffer p
                    unsigned ohv = *(const unsigned*)&hbh[p * TN * SMP + row * SMP + u];
                    unsigned olv = *(const unsigned*)&hbl[p * TN * SMP + row * SMP + u];
                    float ho0 = bflo(ohv) + bflo(olv);
                    float ho1 = bfhi(ohv) + bfhi(olv);
                    float hn0 = (1.f - z0) * n0 + z0 * ho0;
                    float hn1 = (1.f - z1) * n1 + z1 * ho1;
                    __nv_bfloat16 p0 = __float2bfloat16(hn0);
                    __nv_bfloat16 p1 = __float2bfloat16(hn1);
                    // h_t into buffer 1-p (no reader until after the barrier)
                    *(unsigned*)&hbh[(1 - p) * TN * SMP + row * SMP + u] = pk(p0, p1);
                    *(unsigned*)&hbl[(1 - p) * TN * SMP + row * SMP + u] =
                        pk(__float2bfloat16(hn0 - __bfloat162float(p0)),
                           __float2bfloat16(hn1 - __bfloat162float(p1)));
                    pr += hn0 * wox + hn1 * woy;
                }
                pr += __shfl_xor_sync(0xffffffffu, pr, 1);
                pr += __shfl_xor_sync(0xffffffffu, pr, 2);
                if (tg == 0) outb[(t & 1) * 8 * TN + w * TN + row] = pr;
            }
            // this m-tile's accumulators are free: zero + its x-side MMA(t+1)
            #pragma unroll
            for (int s = 0; s < 4; ++s)
                #pragma unroll
                for (int nt = 0; nt < 2; ++nt)
                    #pragma unroll
                    for (int q = 0; q < 4; ++q) acc[s][mt][nt][q] = 0.f;
            if (t < LL - 1)
                xside_mt(acc, mt, xhA[xn], xlA[xn], w, l);
        }

        __syncthreads();   // single barrier: h_t, x_{t+2}, outb(t) all published
    }

    if (tid < TN) {
        float s = bo;
        #pragma unroll
        for (int ww = 0; ww < 8; ++ww)
            s += outb[((LL - 1) & 1) * 8 * TN + ww * TN + tid];
        out[(size_t)(nBase + tid) * LL + (LL - 1)] = s;
    }
}

extern "C" void kernel_launch(void* const* d_in, const int* in_sizes, int n_in,
                              void* d_out, int out_size) {
    const float* item  = (const float*)d_in[0];
    const float* user  = (const float*)d_in[1];
    const float* W_ih  = (const float*)d_in[2];
    const float* W_hh  = (const float*)d_in[3];
    const float* b_ih  = (const float*)d_in[4];
    const float* b_hh  = (const float*)d_in[5];
    const float* W_out = (const float*)d_in[6];
    const float* b_out = (const float*)d_in[7];
    float* out = (float*)d_out;

    prep_weights<<<(4 * 8 * 48 * 32 + 255) / 256, 256>>>(W_ih, W_hh);

    size_t smem = (size_t)(8 * TN * SMP) * sizeof(unsigned short)  // x(2) + h(2), hi+lo
                + 2 * 8 * TN * sizeof(float)   // outb double-buffered
                + 512 * sizeof(float);         // biases
    // 69632 + 2048 + 2048 = 73728 B per CTA -> 147456 B per SM at 2 CTAs
    cudaFuncSetAttribute(gru_mma,
                         cudaFuncAttributeMaxDynamicSharedMemorySize, (int)smem);
    gru_mma<<<NCTA, NTHR, smem>>>(item, user, b_ih, b_hh, W_out, b_out, out);
}

// round 11
// speedup vs baseline: 1.4278x; 1.4278x over previous
#include <cuda_runtime.h>
#include <cuda_fp16.h>
#include <math.h>

// ---------------------------------------------------------------------------
// SlatewiseGRU via tensor cores: mma.sync m16n8k16 fp16, 2-term split
// (x_hi*W + x_lo*W, W rounded to fp16; x/h carried as fp16 hi+lo pairs),
// fp32 accumulate. Schedule = R6 (best measured): TN=32, 256 thr, 2 CTAs/SM,
// 2 barriers/step, x(t+1) register prefetch under the MMA drain.
// 33% fewer HMMAs than the bf16 3-term kernel.
// ---------------------------------------------------------------------------

#define DD   128
#define LL   32
#define NSEQ 8192
#define TN   32
#define NTHR 256
#define NCTA (NSEQ / TN)   // 256
#define SMP  136           // padded SMEM row stride (fp16 elems); row = 272 B

// Packed B-fragments: [wt:2 (ih,hh)][kt:8][ntile:48 (gg*16+w)][lane:32]
__device__ uint2 g_wpack[2 * 8 * 48 * 32];

__global__ void prep_weights(const float* __restrict__ W_ih,
                             const float* __restrict__ W_hh) {
    int idx = blockIdx.x * blockDim.x + threadIdx.x;
    if (idx >= 2 * 8 * 48 * 32) return;
    int l  = idx & 31;
    int r  = idx >> 5;
    int nt = r % 48; r /= 48;
    int kt = r % 8;  r /= 8;
    int wt = r;
    const float* W = wt ? W_hh : W_ih;
    int gg = nt / 16, w = nt % 16;
    int j  = gg * 128 + w * 8 + (l >> 2);     // gate row (B col n = lane>>2)
    int d0 = kt * 16 + (l & 3) * 2;           // k0 = (lane%4)*2
    unsigned short e[4];
    #pragma unroll
    for (int q = 0; q < 4; ++q) {
        int d = d0 + (q & 1) + (q >> 1) * 8;  // b0:{k0,k0+1}  b1:{k0+8,k0+9}
        e[q] = __half_as_ushort(__float2half_rn(W[j * DD + d]));
    }
    uint2 v;
    v.x = (unsigned)e[0] | ((unsigned)e[1] << 16);
    v.y = (unsigned)e[2] | ((unsigned)e[3] << 16);
    g_wpack[idx] = v;
}

__device__ __forceinline__ unsigned pkh(__half a, __half b) {
    return (unsigned)__half_as_ushort(a) | ((unsigned)__half_as_ushort(b) << 16);
}
__device__ __forceinline__ float hlo(unsigned u) {
    return __half2float(__ushort_as_half((unsigned short)(u & 0xffffu)));
}
__device__ __forceinline__ float hhi(unsigned u) {
    return __half2float(__ushort_as_half((unsigned short)(u >> 16)));
}

__device__ __forceinline__ void mma16816(float* c, const unsigned* a, uint2 b) {
    asm volatile(
        "mma.sync.aligned.m16n8k16.row.col.f32.f16.f16.f32 "
        "{%0,%1,%2,%3}, {%4,%5,%6,%7}, {%8,%9}, {%0,%1,%2,%3};\n"
        : "+f"(c[0]), "+f"(c[1]), "+f"(c[2]), "+f"(c[3])
        : "r"(a[0]), "r"(a[1]), "r"(a[2]), "r"(a[3]), "r"(b.x), "r"(b.y));
}

__device__ __forceinline__ void ldsm4(unsigned* r, unsigned addr) {
    asm volatile("ldmatrix.sync.aligned.m8n8.x4.shared.b16 {%0,%1,%2,%3}, [%4];"
                 : "=r"(r[0]), "=r"(r[1]), "=r"(r[2]), "=r"(r[3]) : "r"(addr));
}

__device__ __forceinline__ float sigm(float x) {
    return __fdividef(1.f, 1.f + __expf(-x));
}
__device__ __forceinline__ float tanhfast(float x) {
    return 1.f - __fdividef(2.f, __expf(2.f * x) + 1.f);
}

extern __shared__ char smraw[];

__global__ void __launch_bounds__(NTHR, 2)
gru_mma(const float* __restrict__ item,   // [N, L, D]
        const float* __restrict__ user,   // [N, D]
        const float* __restrict__ b_ih,   // [384]
        const float* __restrict__ b_hh,   // [384]
        const float* __restrict__ W_out,  // [128]
        const float* __restrict__ b_out,  // [1]
        float* __restrict__ out)          // [N, L]
{
    unsigned short* xh = (unsigned short*)smraw;
    unsigned short* xl = xh + TN * SMP;
    unsigned short* hh = xl + TN * SMP;
    unsigned short* hl = hh + TN * SMP;
    float* outb = (float*)(hl + TN * SMP);   // [8][32]
    float* Bs   = outb + 8 * TN;             // [512]

    const int tid = threadIdx.x;
    const int w   = tid >> 5;   // 8 warps
    const int l   = tid & 31;
    const int g   = l >> 2;
    const int tg  = l & 3;
    const int nBase = blockIdx.x * TN;

    // Biases -> SMEM: [0:256) = b_ih+b_hh for r,z; [256:384) = b_ih n;
    // [384:512) = b_hh n.
    for (int i = tid; i < 512; i += NTHR) {
        float v;
        if (i < 256)      v = b_ih[i] + b_hh[i];
        else if (i < 384) v = b_ih[i];
        else              v = b_hh[i - 128];
        Bs[i] = v;
    }

    // ldmatrix per-thread base addresses
    const int rowsel = l & 15;
    const int halfc  = l >> 4;
    const unsigned lmOff = (unsigned)((rowsel * SMP + halfc * 8) * 2);
    const unsigned xhA = (unsigned)__cvta_generic_to_shared(xh) + lmOff;
    const unsigned xlA = (unsigned)__cvta_generic_to_shared(xl) + lmOff;
    const unsigned hhA = (unsigned)__cvta_generic_to_shared(hh) + lmOff;
    const unsigned hlA = (unsigned)__cvta_generic_to_shared(hl) + lmOff;

    // this thread's output units: two groups of 2, in n8-subtiles nt=0,1
    const int ua = w * 16 + tg * 2;       // nt = 0
    const int ub = ua + 8;                // nt = 1
    float2 woA = *(const float2*)(W_out + ua);
    float2 woB = *(const float2*)(W_out + ub);
    const float bo = b_out[0];

    // h0 = user_embs; owner-thread init (fp16 hi/lo split)
    #pragma unroll
    for (int mt = 0; mt < 2; ++mt)
        #pragma unroll
        for (int rh = 0; rh < 2; ++rh) {
            int row = mt * 16 + g + rh * 8;
            #pragma unroll
            for (int nt = 0; nt < 2; ++nt) {
                int u = (nt ? ub : ua);
                float2 v = *(const float2*)(user + (size_t)(nBase + row) * DD + u);
                __half a0 = __float2half_rn(v.x);
                __half a1 = __float2half_rn(v.y);
                *(unsigned*)&hh[row * SMP + u] = pkh(a0, a1);
                *(unsigned*)&hl[row * SMP + u] =
                    pkh(__float2half_rn(v.x - __half2float(a0)),
                        __float2half_rn(v.y - __half2float(a1)));
            }
        }

    // staging coordinates (4 float4 per thread per step: 32 rows x 32 float4)
    int srow[4], scol[4];
    #pragma unroll
    for (int ii = 0; ii < 4; ++ii) {
        int i = tid + ii * NTHR;
        srow[ii] = i >> 5;
        scol[ii] = (i & 31) * 4;
    }

    // prologue: prefetch x_0
    float4 xr[4];
    #pragma unroll
    for (int ii = 0; ii < 4; ++ii)
        xr[ii] = *(const float4*)(item +
                   ((size_t)(nBase + srow[ii]) * LL + 0) * DD + scol[ii]);

    for (int t = 0; t < LL; ++t) {
        // ---- store prefetched x_t into SMEM (fp16 hi/lo split) ----
        #pragma unroll
        for (int ii = 0; ii < 4; ++ii) {
            float4 v = xr[ii];
            __half h0 = __float2half_rn(v.x), h1 = __float2half_rn(v.y);
            __half h2 = __float2half_rn(v.z), h3 = __float2half_rn(v.w);
            uint2 hv, lv;
            hv.x = pkh(h0, h1); hv.y = pkh(h2, h3);
            lv.x = pkh(__float2half_rn(v.x - __half2float(h0)),
                       __float2half_rn(v.y - __half2float(h1)));
            lv.y = pkh(__float2half_rn(v.z - __half2float(h2)),
                       __float2half_rn(v.w - __half2float(h3)));
            *(uint2*)&xh[srow[ii] * SMP + scol[ii]] = hv;
            *(uint2*)&xl[srow[ii] * SMP + scol[ii]] = lv;
        }
        __syncthreads();   // x_t, h(t-1) writes, outb(t-1) all visible

        // ---- finish output of step t-1 ----
        if (t > 0 && tid < TN) {
            float s = bo;
            #pragma unroll
            for (int ww = 0; ww < 8; ++ww) s += outb[ww * TN + tid];
            out[(size_t)(nBase + tid) * LL + (t - 1)] = s;
        }

        // acc[slot r,z,nx,nh][mt:2][nt:2][4]
        float acc[4][2][2][4];
        #pragma unroll
        for (int s = 0; s < 4; ++s)
            #pragma unroll
            for (int mt = 0; mt < 2; ++mt)
                #pragma unroll
                for (int nt = 0; nt < 2; ++nt)
                    #pragma unroll
                    for (int q = 0; q < 4; ++q) acc[s][mt][nt][q] = 0.f;

        // ---- GEMM: 2 sides x 8 kt x (hi + lo terms), single W plane ----
        #pragma unroll
        for (int ph = 0; ph < 2; ++ph) {
            const unsigned aH = ph ? hhA : xhA;
            const unsigned aL = ph ? hlA : xlA;
            const int ns  = ph ? 3 : 2;    // n-gate accumulator slot

            #pragma unroll
            for (int kt = 0; kt < 8; ++kt) {
                uint2 Bw[3][2];
                #pragma unroll
                for (int gg = 0; gg < 3; ++gg)
                    #pragma unroll
                    for (int nt = 0; nt < 2; ++nt) {
                        int off = (gg * 16 + 2 * w + nt) * 32 + l;
                        Bw[gg][nt] = g_wpack[(ph * 8 + kt) * 1536 + off];
                    }
                unsigned a[2][4];
                #pragma unroll
                for (int mt = 0; mt < 2; ++mt)
                    ldsm4(a[mt], aH + mt * (16 * SMP * 2) + kt * 32);
                #pragma unroll
                for (int gg = 0; gg < 3; ++gg) {
                    const int s = (gg < 2) ? gg : ns;
                    #pragma unroll
                    for (int nt = 0; nt < 2; ++nt)
                        #pragma unroll
                        for (int mt = 0; mt < 2; ++mt)
                            mma16816(acc[s][mt][nt], a[mt], Bw[gg][nt]);
                }
                #pragma unroll
                for (int mt = 0; mt < 2; ++mt)
                    ldsm4(a[mt], aL + mt * (16 * SMP * 2) + kt * 32);
                #pragma unroll
                for (int gg = 0; gg < 3; ++gg) {
                    const int s = (gg < 2) ? gg : ns;
                    #pragma unroll
                    for (int nt = 0; nt < 2; ++nt)
                        #pragma unroll
                        for (int mt = 0; mt < 2; ++mt)
                            mma16816(acc[s][mt][nt], a[mt], Bw[gg][nt]);
                }
            }
        }

        // ---- prefetch x_{t+1} while MMAs drain ----
        if (t < LL - 1) {
            #pragma unroll
            for (int ii = 0; ii < 4; ++ii)
                xr[ii] = *(const float4*)(item +
                           ((size_t)(nBase + srow[ii]) * LL + (t + 1)) * DD + scol[ii]);
        }
        __syncthreads();   // all SMEM A reads complete

        // ---- epilogue: gates, h update, output partials ----
        #pragma unroll
        for (int mt = 0; mt < 2; ++mt)
            #pragma unroll
            for (int rh = 0; rh < 2; ++rh) {
                int row = mt * 16 + g + rh * 8;
                float p = 0.f;
                #pragma unroll
                for (int nt = 0; nt < 2; ++nt) {
                    int u = (nt ? ub : ua);
                    float wox = nt ? woB.x : woA.x;
                    float woy = nt ? woB.y : woA.y;
                    float r0 = sigm(acc[0][mt][nt][rh * 2]     + Bs[u]);
                    float r1 = sigm(acc[0][mt][nt][rh * 2 + 1] + Bs[u + 1]);
                    float z0 = sigm(acc[1][mt][nt][rh * 2]     + Bs[128 + u]);
                    float z1 = sigm(acc[1][mt][nt][rh * 2 + 1] + Bs[128 + u + 1]);
                    float n0 = tanhfast(acc[2][mt][nt][rh * 2] + Bs[256 + u]
                               + r0 * (acc[3][mt][nt][rh * 2]  + Bs[384 + u]));
                    float n1 = tanhfast(acc[2][mt][nt][rh * 2 + 1] + Bs[256 + u + 1]
                               + r1 * (acc[3][mt][nt][rh * 2 + 1]  + Bs[384 + u + 1]));
                    unsigned ohv = *(const unsigned*)&hh[row * SMP + u];
                    unsigned olv = *(const unsigned*)&hl[row * SMP + u];
                    float ho0 = hlo(ohv) + hlo(olv);
                    float ho1 = hhi(ohv) + hhi(olv);
                    float hn0 = (1.f - z0) * n0 + z0 * ho0;
                    float hn1 = (1.f - z1) * n1 + z1 * ho1;
                    __half p0 = __float2half_rn(hn0);
                    __half p1 = __float2half_rn(hn1);
                    *(unsigned*)&hh[row * SMP + u] = pkh(p0, p1);
                    *(unsigned*)&hl[row * SMP + u] =
                        pkh(__float2half_rn(hn0 - __half2float(p0)),
                            __float2half_rn(hn1 - __half2float(p1)));
                    p += hn0 * wox + hn1 * woy;
                }
                p += __shfl_xor_sync(0xffffffffu, p, 1);
                p += __shfl_xor_sync(0xffffffffu, p, 2);
                if (tg == 0) outb[w * TN + row] = p;
            }
        // next iteration's first barrier covers outb/h visibility
    }

    __syncthreads();
    if (tid < TN) {
        float s = bo;
        #pragma unroll
        for (int ww = 0; ww < 8; ++ww) s += outb[ww * TN + tid];
        out[(size_t)(nBase + tid) * LL + (LL - 1)] = s;
    }
}

extern "C" void kernel_launch(void* const* d_in, const int* in_sizes, int n_in,
                              void* d_out, int out_size) {
    const float* item  = (const float*)d_in[0];
    const float* user  = (const float*)d_in[1];
    const float* W_ih  = (const float*)d_in[2];
    const float* W_hh  = (const float*)d_in[3];
    const float* b_ih  = (const float*)d_in[4];
    const float* b_hh  = (const float*)d_in[5];
    const float* W_out = (const float*)d_in[6];
    const float* b_out = (const float*)d_in[7];
    float* out = (float*)d_out;

    prep_weights<<<(2 * 8 * 48 * 32 + 255) / 256, 256>>>(W_ih, W_hh);

    size_t smem = (size_t)(4 * TN * SMP) * sizeof(unsigned short)
                + 8 * TN * sizeof(float)        // outb
                + 512 * sizeof(float);          // biases
    // 34816 + 1024 + 2048 = 37888 B per CTA -> 75776 B per SM at 2 CTAs
    cudaFuncSetAttribute(gru_mma,
                         cudaFuncAttributeMaxDynamicSharedMemorySize, (int)smem);
    gru_mma<<<NCTA, NTHR, smem>>>(item, user, b_ih, b_hh, W_out, b_out, out);
}

// round 12
// speedup vs baseline: 1.8044x; 1.2638x over previous
#include <cuda_runtime.h>
#include <cuda_fp16.h>
#include <math.h>

// ---------------------------------------------------------------------------
// SlatewiseGRU via tensor cores: mma.sync m16n8k16 fp16, fp32 accumulate.
// R11: x as a SINGLE fp16 plane (x-side = 1 MMA term); h kept as fp16 hi+lo
// 2-term split (recurrence precision). Epilogue nonlinearity via MUFU.TANH
// (tanh.approx.f32; sigmoid = 0.5*tanh(x/2)+0.5): 48 MUFU/thread/step vs 96.
// Schedule = R10 (best measured): TN=32, 256 thr, 2 CTAs/SM, 2 barriers/step,
// x(t+1) register prefetch under the MMA drain. 144 HMMA/warp/step.
// ---------------------------------------------------------------------------

#define DD   128
#define LL   32
#define NSEQ 8192
#define TN   32
#define NTHR 256
#define NCTA (NSEQ / TN)   // 256
#define SMP  136           // padded SMEM row stride (fp16 elems); row = 272 B

// Packed B-fragments: [wt:2 (ih,hh)][kt:8][ntile:48 (gg*16+w)][lane:32]
__device__ uint2 g_wpack[2 * 8 * 48 * 32];

__global__ void prep_weights(const float* __restrict__ W_ih,
                             const float* __restrict__ W_hh) {
    int idx = blockIdx.x * blockDim.x + threadIdx.x;
    if (idx >= 2 * 8 * 48 * 32) return;
    int l  = idx & 31;
    int r  = idx >> 5;
    int nt = r % 48; r /= 48;
    int kt = r % 8;  r /= 8;
    int wt = r;
    const float* W = wt ? W_hh : W_ih;
    int gg = nt / 16, w = nt % 16;
    int j  = gg * 128 + w * 8 + (l >> 2);     // gate row (B col n = lane>>2)
    int d0 = kt * 16 + (l & 3) * 2;           // k0 = (lane%4)*2
    unsigned short e[4];
    #pragma unroll
    for (int q = 0; q < 4; ++q) {
        int d = d0 + (q & 1) + (q >> 1) * 8;  // b0:{k0,k0+1}  b1:{k0+8,k0+9}
        e[q] = __half_as_ushort(__float2half_rn(W[j * DD + d]));
    }
    uint2 v;
    v.x = (unsigned)e[0] | ((unsigned)e[1] << 16);
    v.y = (unsigned)e[2] | ((unsigned)e[3] << 16);
    g_wpack[idx] = v;
}

__device__ __forceinline__ unsigned pkh(__half a, __half b) {
    return (unsigned)__half_as_ushort(a) | ((unsigned)__half_as_ushort(b) << 16);
}
__device__ __forceinline__ float hlo(unsigned u) {
    return __half2float(__ushort_as_half((unsigned short)(u & 0xffffu)));
}
__device__ __forceinline__ float hhi(unsigned u) {
    return __half2float(__ushort_as_half((unsigned short)(u >> 16)));
}

__device__ __forceinline__ void mma16816(float* c, const unsigned* a, uint2 b) {
    asm volatile(
        "mma.sync.aligned.m16n8k16.row.col.f32.f16.f16.f32 "
        "{%0,%1,%2,%3}, {%4,%5,%6,%7}, {%8,%9}, {%0,%1,%2,%3};\n"
        : "+f"(c[0]), "+f"(c[1]), "+f"(c[2]), "+f"(c[3])
        : "r"(a[0]), "r"(a[1]), "r"(a[2]), "r"(a[3]), "r"(b.x), "r"(b.y));
}

__device__ __forceinline__ void ldsm4(unsigned* r, unsigned addr) {
    asm volatile("ldmatrix.sync.aligned.m8n8.x4.shared.b16 {%0,%1,%2,%3}, [%4];"
                 : "=r"(r[0]), "=r"(r[1]), "=r"(r[2]), "=r"(r[3]) : "r"(addr));
}

// MUFU.TANH (sm_75+): one MUFU op, ~2^-11 abs error.
__device__ __forceinline__ float tanh_mufu(float x) {
    float y;
    asm("tanh.approx.f32 %0, %1;" : "=f"(y) : "f"(x));
    return y;
}
__device__ __forceinline__ float sigm(float x) {   // 1 MUFU + FMA
    return fmaf(tanh_mufu(0.5f * x), 0.5f, 0.5f);
}

extern __shared__ char smraw[];

__global__ void __launch_bounds__(NTHR, 2)
gru_mma(const float* __restrict__ item,   // [N, L, D]
        const float* __restrict__ user,   // [N, D]
        const float* __restrict__ b_ih,   // [384]
        const float* __restrict__ b_hh,   // [384]
        const float* __restrict__ W_out,  // [128]
        const float* __restrict__ b_out,  // [1]
        float* __restrict__ out)          // [N, L]
{
    unsigned short* xh = (unsigned short*)smraw;      // x, single fp16 plane
    unsigned short* hh = xh + TN * SMP;               // h hi
    unsigned short* hl = hh + TN * SMP;               // h lo
    float* outb = (float*)(hl + TN * SMP);            // [8][32]
    float* Bs   = outb + 8 * TN;                      // [512]

    const int tid = threadIdx.x;
    const int w   = tid >> 5;   // 8 warps
    const int l   = tid & 31;
    const int g   = l >> 2;
    const int tg  = l & 3;
    const int nBase = blockIdx.x * TN;

    // Biases -> SMEM: [0:256) = b_ih+b_hh for r,z; [256:384) = b_ih n;
    // [384:512) = b_hh n.
    for (int i = tid; i < 512; i += NTHR) {
        float v;
        if (i < 256)      v = b_ih[i] + b_hh[i];
        else if (i < 384) v = b_ih[i];
        else              v = b_hh[i - 128];
        Bs[i] = v;
    }

    // ldmatrix per-thread base addresses
    const int rowsel = l & 15;
    const int halfc  = l >> 4;
    const unsigned lmOff = (unsigned)((rowsel * SMP + halfc * 8) * 2);
    const unsigned xhA = (unsigned)__cvta_generic_to_shared(xh) + lmOff;
    const unsigned hhA = (unsigned)__cvta_generic_to_shared(hh) + lmOff;
    const unsigned hlA = (unsigned)__cvta_generic_to_shared(hl) + lmOff;

    // this thread's output units: two groups of 2, in n8-subtiles nt=0,1
    const int ua = w * 16 + tg * 2;       // nt = 0
    const int ub = ua + 8;                // nt = 1
    float2 woA = *(const float2*)(W_out + ua);
    float2 woB = *(const float2*)(W_out + ub);
    const float bo = b_out[0];

    // h0 = user_embs; owner-thread init (fp16 hi/lo split)
    #pragma unroll
    for (int mt = 0; mt < 2; ++mt)
        #pragma unroll
        for (int rh = 0; rh < 2; ++rh) {
            int row = mt * 16 + g + rh * 8;
            #pragma unroll
            for (int nt = 0; nt < 2; ++nt) {
                int u = (nt ? ub : ua);
                float2 v = *(const float2*)(user + (size_t)(nBase + row) * DD + u);
                __half a0 = __float2half_rn(v.x);
                __half a1 = __float2half_rn(v.y);
                *(unsigned*)&hh[row * SMP + u] = pkh(a0, a1);
                *(unsigned*)&hl[row * SMP + u] =
                    pkh(__float2half_rn(v.x - __half2float(a0)),
                        __float2half_rn(v.y - __half2float(a1)));
            }
        }

    // staging coordinates (4 float4 per thread per step: 32 rows x 32 float4)
    int srow[4], scol[4];
    #pragma unroll
    for (int ii = 0; ii < 4; ++ii) {
        int i = tid + ii * NTHR;
        srow[ii] = i >> 5;
        scol[ii] = (i & 31) * 4;
    }

    // prologue: prefetch x_0
    float4 xr[4];
    #pragma unroll
    for (int ii = 0; ii < 4; ++ii)
        xr[ii] = *(const float4*)(item +
                   ((size_t)(nBase + srow[ii]) * LL + 0) * DD + scol[ii]);

    for (int t = 0; t < LL; ++t) {
        // ---- store prefetched x_t into SMEM (single fp16 plane) ----
        #pragma unroll
        for (int ii = 0; ii < 4; ++ii) {
            float4 v = xr[ii];
            uint2 hv;
            hv.x = pkh(__float2half_rn(v.x), __float2half_rn(v.y));
            hv.y = pkh(__float2half_rn(v.z), __float2half_rn(v.w));
            *(uint2*)&xh[srow[ii] * SMP + scol[ii]] = hv;
        }
        __syncthreads();   // x_t, h(t-1) writes, outb(t-1) all visible

        // ---- finish output of step t-1 ----
        if (t > 0 && tid < TN) {
            float s = bo;
            #pragma unroll
            for (int ww = 0; ww < 8; ++ww) s += outb[ww * TN + tid];
            out[(size_t)(nBase + tid) * LL + (t - 1)] = s;
        }

        // acc[slot r,z,nx,nh][mt:2][nt:2][4]
        float acc[4][2][2][4];
        #pragma unroll
        for (int s = 0; s < 4; ++s)
            #pragma unroll
            for (int mt = 0; mt < 2; ++mt)
                #pragma unroll
                for (int nt = 0; nt < 2; ++nt)
                    #pragma unroll
                    for (int q = 0; q < 4; ++q) acc[s][mt][nt][q] = 0.f;

        // ---- GEMM: x-side (1 term) + h-side (hi+lo), single W plane ----
        #pragma unroll
        for (int kt = 0; kt < 8; ++kt) {       // x-side
            uint2 Bw[3][2];
            #pragma unroll
            for (int gg = 0; gg < 3; ++gg)
                #pragma unroll
                for (int nt = 0; nt < 2; ++nt) {
                    int off = (gg * 16 + 2 * w + nt) * 32 + l;
                    Bw[gg][nt] = g_wpack[kt * 1536 + off];
                }
            unsigned a[2][4];
            #pragma unroll
            for (int mt = 0; mt < 2; ++mt)
                ldsm4(a[mt], xhA + mt * (16 * SMP * 2) + kt * 32);
            #pragma unroll
            for (int gg = 0; gg < 3; ++gg) {
                const int s = (gg < 2) ? gg : 2;
                #pragma unroll
                for (int nt = 0; nt < 2; ++nt)
                    #pragma unroll
                    for (int mt = 0; mt < 2; ++mt)
                        mma16816(acc[s][mt][nt], a[mt], Bw[gg][nt]);
            }
        }
        #pragma unroll
        for (int kt = 0; kt < 8; ++kt) {       // h-side, 2 terms
            uint2 Bw[3][2];
            #pragma unroll
            for (int gg = 0; gg < 3; ++gg)
                #pragma unroll
                for (int nt = 0; nt < 2; ++nt) {
                    int off = (gg * 16 + 2 * w + nt) * 32 + l;
                    Bw[gg][nt] = g_wpack[(8 + kt) * 1536 + off];
                }
            unsigned a[2][4];
            #pragma unroll
            for (int mt = 0; mt < 2; ++mt)
                ldsm4(a[mt], hhA + mt * (16 * SMP * 2) + kt * 32);
            #pragma unroll
            for (int gg = 0; gg < 3; ++gg) {
                const int s = (gg < 2) ? gg : 3;
                #pragma unroll
                for (int nt = 0; nt < 2; ++nt)
                    #pragma unroll
                    for (int mt = 0; mt < 2; ++mt)
                        mma16816(acc[s][mt][nt], a[mt], Bw[gg][nt]);
            }
            #pragma unroll
            for (int mt = 0; mt < 2; ++mt)
                ldsm4(a[mt], hlA + mt * (16 * SMP * 2) + kt * 32);
            #pragma unroll
            for (int gg = 0; gg < 3; ++gg) {
                const int s = (gg < 2) ? gg : 3;
                #pragma unroll
                for (int nt = 0; nt < 2; ++nt)
                    #pragma unroll
                    for (int mt = 0; mt < 2; ++mt)
                        mma16816(acc[s][mt][nt], a[mt], Bw[gg][nt]);
            }
        }

        // ---- prefetch x_{t+1} while MMAs drain ----
        if (t < LL - 1) {
            #pragma unroll
            for (int ii = 0; ii < 4; ++ii)
                xr[ii] = *(const float4*)(item +
                           ((size_t)(nBase + srow[ii]) * LL + (t + 1)) * DD + scol[ii]);
        }
        __syncthreads();   // all SMEM A reads complete

        // ---- epilogue: gates (MUFU.TANH), h update, output partials ----
        #pragma unroll
        for (int mt = 0; mt < 2; ++mt)
            #pragma unroll
            for (int rh = 0; rh < 2; ++rh) {
                int row = mt * 16 + g + rh * 8;
                float p = 0.f;
                #pragma unroll
                for (int nt = 0; nt < 2; ++nt) {
                    int u = (nt ? ub : ua);
                    float wox = nt ? woB.x : woA.x;
                    float woy = nt ? woB.y : woA.y;
                    float r0 = sigm(acc[0][mt][nt][rh * 2]     + Bs[u]);
                    float r1 = sigm(acc[0][mt][nt][rh * 2 + 1] + Bs[u + 1]);
                    float z0 = sigm(acc[1][mt][nt][rh * 2]     + Bs[128 + u]);
                    float z1 = sigm(acc[1][mt][nt][rh * 2 + 1] + Bs[128 + u + 1]);
                    float n0 = tanh_mufu(acc[2][mt][nt][rh * 2] + Bs[256 + u]
                               + r0 * (acc[3][mt][nt][rh * 2]   + Bs[384 + u]));
                    float n1 = tanh_mufu(acc[2][mt][nt][rh * 2 + 1] + Bs[256 + u + 1]
                               + r1 * (acc[3][mt][nt][rh * 2 + 1]   + Bs[384 + u + 1]));
                    unsigned ohv = *(const unsigned*)&hh[row * SMP + u];
                    unsigned olv = *(const unsigned*)&hl[row * SMP + u];
                    float ho0 = hlo(ohv) + hlo(olv);
                    float ho1 = hhi(ohv) + hhi(olv);
                    float hn0 = (1.f - z0) * n0 + z0 * ho0;
                    float hn1 = (1.f - z1) * n1 + z1 * ho1;
                    __half p0 = __float2half_rn(hn0);
                    __half p1 = __float2half_rn(hn1);
                    *(unsigned*)&hh[row * SMP + u] = pkh(p0, p1);
                    *(unsigned*)&hl[row * SMP + u] =
                        pkh(__float2half_rn(hn0 - __half2float(p0)),
                            __float2half_rn(hn1 - __half2float(p1)));
                    p += hn0 * wox + hn1 * woy;
                }
                p += __shfl_xor_sync(0xffffffffu, p, 1);
                p += __shfl_xor_sync(0xffffffffu, p, 2);
                if (tg == 0) outb[w * TN + row] = p;
            }
        // next iteration's first barrier covers outb/h visibility
    }

    __syncthreads();
    if (tid < TN) {
        float s = bo;
        #pragma unroll
        for (int ww = 0; ww < 8; ++ww) s += outb[ww * TN + tid];
        out[(size_t)(nBase + tid) * LL + (LL - 1)] = s;
    }
}

extern "C" void kernel_launch(void* const* d_in, const int* in_sizes, int n_in,
                              void* d_out, int out_size) {
    const float* item  = (const float*)d_in[0];
    const float* user  = (const float*)d_in[1];
    const float* W_ih  = (const float*)d_in[2];
    const float* W_hh  = (const float*)d_in[3];
    const float* b_ih  = (const float*)d_in[4];
    const float* b_hh  = (const float*)d_in[5];
    const float* W_out = (const float*)d_in[6];
    const float* b_out = (const float*)d_in[7];
    float* out = (float*)d_out;

    prep_weights<<<(2 * 8 * 48 * 32 + 255) / 256, 256>>>(W_ih, W_hh);

    size_t smem = (size_t)(3 * TN * SMP) * sizeof(unsigned short)  // x + h(hi,lo)
                + 8 * TN * sizeof(float)        // outb
                + 512 * sizeof(float);          // biases
    // 26112 + 1024 + 2048 = 29184 B per CTA -> 58368 B per SM at 2 CTAs
    cudaFuncSetAttribute(gru_mma,
                         cudaFuncAttributeMaxDynamicSharedMemorySize, (int)smem);
    gru_mma<<<NCTA, NTHR, smem>>>(item, user, b_ih, b_hh, W_out, b_out, out);
}

// round 13
// speedup vs baseline: 2.3117x; 1.2812x over previous
#include <cuda_runtime.h>
#include <cuda_fp16.h>
#include <math.h>

// ---------------------------------------------------------------------------
// SlatewiseGRU via tensor cores: mma.sync m16n8k16 fp16, fp32 accumulate.
// R12: BOTH GEMM inputs single fp16 plane (x_hi*W + h_hi*W) -> 96 HMMA/warp/
// step. h STATE still stored as fp16 hi+lo (convex update uses accurate
// h_old; only the matvec input is quantized). Epilogue via MUFU.TANH.
// Schedule = R10/R11 (measured best): TN=32, 256 thr, 2 CTAs/SM,
// 2 barriers/step, x(t+1) register prefetch under the MMA drain.
// ---------------------------------------------------------------------------

#define DD   128
#define LL   32
#define NSEQ 8192
#define TN   32
#define NTHR 256
#define NCTA (NSEQ / TN)   // 256
#define SMP  136           // padded SMEM row stride (fp16 elems); row = 272 B

// Packed B-fragments: [wt:2 (ih,hh)][kt:8][ntile:48 (gg*16+w)][lane:32]
__device__ uint2 g_wpack[2 * 8 * 48 * 32];

__global__ void prep_weights(const float* __restrict__ W_ih,
                             const float* __restrict__ W_hh) {
    int idx = blockIdx.x * blockDim.x + threadIdx.x;
    if (idx >= 2 * 8 * 48 * 32) return;
    int l  = idx & 31;
    int r  = idx >> 5;
    int nt = r % 48; r /= 48;
    int kt = r % 8;  r /= 8;
    int wt = r;
    const float* W = wt ? W_hh : W_ih;
    int gg = nt / 16, w = nt % 16;
    int j  = gg * 128 + w * 8 + (l >> 2);     // gate row (B col n = lane>>2)
    int d0 = kt * 16 + (l & 3) * 2;           // k0 = (lane%4)*2
    unsigned short e[4];
    #pragma unroll
    for (int q = 0; q < 4; ++q) {
        int d = d0 + (q & 1) + (q >> 1) * 8;  // b0:{k0,k0+1}  b1:{k0+8,k0+9}
        e[q] = __half_as_ushort(__float2half_rn(W[j * DD + d]));
    }
    uint2 v;
    v.x = (unsigned)e[0] | ((unsigned)e[1] << 16);
    v.y = (unsigned)e[2] | ((unsigned)e[3] << 16);
    g_wpack[idx] = v;
}

__device__ __forceinline__ unsigned pkh(__half a, __half b) {
    return (unsigned)__half_as_ushort(a) | ((unsigned)__half_as_ushort(b) << 16);
}
__device__ __forceinline__ float hlo(unsigned u) {
    return __half2float(__ushort_as_half((unsigned short)(u & 0xffffu)));
}
__device__ __forceinline__ float hhi(unsigned u) {
    return __half2float(__ushort_as_half((unsigned short)(u >> 16)));
}

__device__ __forceinline__ void mma16816(float* c, const unsigned* a, uint2 b) {
    asm volatile(
        "mma.sync.aligned.m16n8k16.row.col.f32.f16.f16.f32 "
        "{%0,%1,%2,%3}, {%4,%5,%6,%7}, {%8,%9}, {%0,%1,%2,%3};\n"
        : "+f"(c[0]), "+f"(c[1]), "+f"(c[2]), "+f"(c[3])
        : "r"(a[0]), "r"(a[1]), "r"(a[2]), "r"(a[3]), "r"(b.x), "r"(b.y));
}

__device__ __forceinline__ void ldsm4(unsigned* r, unsigned addr) {
    asm volatile("ldmatrix.sync.aligned.m8n8.x4.shared.b16 {%0,%1,%2,%3}, [%4];"
                 : "=r"(r[0]), "=r"(r[1]), "=r"(r[2]), "=r"(r[3]) : "r"(addr));
}

// MUFU.TANH (sm_75+): one MUFU op, ~2^-11 abs error.
__device__ __forceinline__ float tanh_mufu(float x) {
    float y;
    asm("tanh.approx.f32 %0, %1;" : "=f"(y) : "f"(x));
    return y;
}
__device__ __forceinline__ float sigm(float x) {   // 1 MUFU + FMA
    return fmaf(tanh_mufu(0.5f * x), 0.5f, 0.5f);
}

extern __shared__ char smraw[];

__global__ void __launch_bounds__(NTHR, 2)
gru_mma(const float* __restrict__ item,   // [N, L, D]
        const float* __restrict__ user,   // [N, D]
        const float* __restrict__ b_ih,   // [384]
        const float* __restrict__ b_hh,   // [384]
        const float* __restrict__ W_out,  // [128]
        const float* __restrict__ b_out,  // [1]
        float* __restrict__ out)          // [N, L]
{
    unsigned short* xh = (unsigned short*)smraw;      // x, single fp16 plane
    unsigned short* hh = xh + TN * SMP;               // h hi (MMA input)
    unsigned short* hl = hh + TN * SMP;               // h lo (state only)
    float* outb = (float*)(hl + TN * SMP);            // [8][32]
    float* Bs   = outb + 8 * TN;                      // [512]

    const int tid = threadIdx.x;
    const int w   = tid >> 5;   // 8 warps
    const int l   = tid & 31;
    const int g   = l >> 2;
    const int tg  = l & 3;
    const int nBase = blockIdx.x * TN;

    // Biases -> SMEM: [0:256) = b_ih+b_hh for r,z; [256:384) = b_ih n;
    // [384:512) = b_hh n.
    for (int i = tid; i < 512; i += NTHR) {
        float v;
        if (i < 256)      v = b_ih[i] + b_hh[i];
        else if (i < 384) v = b_ih[i];
        else              v = b_hh[i - 128];
        Bs[i] = v;
    }

    // ldmatrix per-thread base addresses
    const int rowsel = l & 15;
    const int halfc  = l >> 4;
    const unsigned lmOff = (unsigned)((rowsel * SMP + halfc * 8) * 2);
    const unsigned xhA = (unsigned)__cvta_generic_to_shared(xh) + lmOff;
    const unsigned hhA = (unsigned)__cvta_generic_to_shared(hh) + lmOff;

    // this thread's output units: two groups of 2, in n8-subtiles nt=0,1
    const int ua = w * 16 + tg * 2;       // nt = 0
    const int ub = ua + 8;                // nt = 1
    float2 woA = *(const float2*)(W_out + ua);
    float2 woB = *(const float2*)(W_out + ub);
    const float bo = b_out[0];

    // h0 = user_embs; owner-thread init (fp16 hi/lo split)
    #pragma unroll
    for (int mt = 0; mt < 2; ++mt)
        #pragma unroll
        for (int rh = 0; rh < 2; ++rh) {
            int row = mt * 16 + g + rh * 8;
            #pragma unroll
            for (int nt = 0; nt < 2; ++nt) {
                int u = (nt ? ub : ua);
                float2 v = *(const float2*)(user + (size_t)(nBase + row) * DD + u);
                __half a0 = __float2half_rn(v.x);
                __half a1 = __float2half_rn(v.y);
                *(unsigned*)&hh[row * SMP + u] = pkh(a0, a1);
                *(unsigned*)&hl[row * SMP + u] =
                    pkh(__float2half_rn(v.x - __half2float(a0)),
                        __float2half_rn(v.y - __half2float(a1)));
            }
        }

    // staging coordinates (4 float4 per thread per step: 32 rows x 32 float4)
    int srow[4], scol[4];
    #pragma unroll
    for (int ii = 0; ii < 4; ++ii) {
        int i = tid + ii * NTHR;
        srow[ii] = i >> 5;
        scol[ii] = (i & 31) * 4;
    }

    // prologue: prefetch x_0
    float4 xr[4];
    #pragma unroll
    for (int ii = 0; ii < 4; ++ii)
        xr[ii] = *(const float4*)(item +
                   ((size_t)(nBase + srow[ii]) * LL + 0) * DD + scol[ii]);

    for (int t = 0; t < LL; ++t) {
        // ---- store prefetched x_t into SMEM (single fp16 plane) ----
        #pragma unroll
        for (int ii = 0; ii < 4; ++ii) {
            float4 v = xr[ii];
            uint2 hv;
            hv.x = pkh(__float2half_rn(v.x), __float2half_rn(v.y));
            hv.y = pkh(__float2half_rn(v.z), __float2half_rn(v.w));
            *(uint2*)&xh[srow[ii] * SMP + scol[ii]] = hv;
        }
        __syncthreads();   // x_t, h(t-1) writes, outb(t-1) all visible

        // ---- finish output of step t-1 ----
        if (t > 0 && tid < TN) {
            float s = bo;
            #pragma unroll
            for (int ww = 0; ww < 8; ++ww) s += outb[ww * TN + tid];
            out[(size_t)(nBase + tid) * LL + (t - 1)] = s;
        }

        // acc[slot r,z,nx,nh][mt:2][nt:2][4]
        float acc[4][2][2][4];
        #pragma unroll
        for (int s = 0; s < 4; ++s)
            #pragma unroll
            for (int mt = 0; mt < 2; ++mt)
                #pragma unroll
                for (int nt = 0; nt < 2; ++nt)
                    #pragma unroll
                    for (int q = 0; q < 4; ++q) acc[s][mt][nt][q] = 0.f;

        // ---- GEMM: x-side (1 term) + h-side (1 term), single W plane ----
        #pragma unroll
        for (int kt = 0; kt < 8; ++kt) {       // x-side
            uint2 Bw[3][2];
            #pragma unroll
            for (int gg = 0; gg < 3; ++gg)
                #pragma unroll
                for (int nt = 0; nt < 2; ++nt) {
                    int off = (gg * 16 + 2 * w + nt) * 32 + l;
                    Bw[gg][nt] = g_wpack[kt * 1536 + off];
                }
            unsigned a[2][4];
            #pragma unroll
            for (int mt = 0; mt < 2; ++mt)
                ldsm4(a[mt], xhA + mt * (16 * SMP * 2) + kt * 32);
            #pragma unroll
            for (int gg = 0; gg < 3; ++gg) {
                const int s = (gg < 2) ? gg : 2;
                #pragma unroll
                for (int nt = 0; nt < 2; ++nt)
                    #pragma unroll
                    for (int mt = 0; mt < 2; ++mt)
                        mma16816(acc[s][mt][nt], a[mt], Bw[gg][nt]);
            }
        }
        #pragma unroll
        for (int kt = 0; kt < 8; ++kt) {       // h-side, single plane
            uint2 Bw[3][2];
            #pragma unroll
            for (int gg = 0; gg < 3; ++gg)
                #pragma unroll
                for (int nt = 0; nt < 2; ++nt) {
                    int off = (gg * 16 + 2 * w + nt) * 32 + l;
                    Bw[gg][nt] = g_wpack[(8 + kt) * 1536 + off];
                }
            unsigned a[2][4];
            #pragma unroll
            for (int mt = 0; mt < 2; ++mt)
                ldsm4(a[mt], hhA + mt * (16 * SMP * 2) + kt * 32);
            #pragma unroll
            for (int gg = 0; gg < 3; ++gg) {
                const int s = (gg < 2) ? gg : 3;
                #pragma unroll
                for (int nt = 0; nt < 2; ++nt)
                    #pragma unroll
                    for (int mt = 0; mt < 2; ++mt)
                        mma16816(acc[s][mt][nt], a[mt], Bw[gg][nt]);
            }
        }

        // ---- prefetch x_{t+1} while MMAs drain ----
        if (t < LL - 1) {
            #pragma unroll
            for (int ii = 0; ii < 4; ++ii)
                xr[ii] = *(const float4*)(item +
                           ((size_t)(nBase + srow[ii]) * LL + (t + 1)) * DD + scol[ii]);
        }
        __syncthreads();   // all SMEM A reads complete

        // ---- epilogue: gates (MUFU.TANH), h update, output partials ----
        #pragma unroll
        for (int mt = 0; mt < 2; ++mt)
            #pragma unroll
            for (int rh = 0; rh < 2; ++rh) {
                int row = mt * 16 + g + rh * 8;
                float p = 0.f;
                #pragma unroll
                for (int nt = 0; nt < 2; ++nt) {
                    int u = (nt ? ub : ua);
                    float wox = nt ? woB.x : woA.x;
                    float woy = nt ? woB.y : woA.y;
                    float r0 = sigm(acc[0][mt][nt][rh * 2]     + Bs[u]);
                    float r1 = sigm(acc[0][mt][nt][rh * 2 + 1] + Bs[u + 1]);
                    float z0 = sigm(acc[1][mt][nt][rh * 2]     + Bs[128 + u]);
                    float z1 = sigm(acc[1][mt][nt][rh * 2 + 1] + Bs[128 + u + 1]);
                    float n0 = tanh_mufu(acc[2][mt][nt][rh * 2] + Bs[256 + u]
                               + r0 * (acc[3][mt][nt][rh * 2]   + Bs[384 + u]));
                    float n1 = tanh_mufu(acc[2][mt][nt][rh * 2 + 1] + Bs[256 + u + 1]
                               + r1 * (acc[3][mt][nt][rh * 2 + 1]   + Bs[384 + u + 1]));
                    // accurate h_old = hi + lo (state kept to ~2^-22)
                    unsigned ohv = *(const unsigned*)&hh[row * SMP + u];
                    unsigned olv = *(const unsigned*)&hl[row * SMP + u];
                    float ho0 = hlo(ohv) + hlo(olv);
                    float ho1 = hhi(ohv) + hhi(olv);
                    float hn0 = (1.f - z0) * n0 + z0 * ho0;
                    float hn1 = (1.f - z1) * n1 + z1 * ho1;
                    __half p0 = __float2half_rn(hn0);
                    __half p1 = __float2half_rn(hn1);
                    *(unsigned*)&hh[row * SMP + u] = pkh(p0, p1);
                    *(unsigned*)&hl[row * SMP + u] =
                        pkh(__float2half_rn(hn0 - __half2float(p0)),
                            __float2half_rn(hn1 - __half2float(p1)));
                    p += hn0 * wox + hn1 * woy;
                }
                p += __shfl_xor_sync(0xffffffffu, p, 1);
                p += __shfl_xor_sync(0xffffffffu, p, 2);
                if (tg == 0) outb[w * TN + row] = p;
            }
        // next iteration's first barrier covers outb/h visibility
    }

    __syncthreads();
    if (tid < TN) {
        float s = bo;
        #pragma unroll
        for (int ww = 0; ww < 8; ++ww) s += outb[ww * TN + tid];
        out[(size_t)(nBase + tid) * LL + (LL - 1)] = s;
    }
}

extern "C" void kernel_launch(void* const* d_in, const int* in_sizes, int n_in,
                              void* d_out, int out_size) {
    const float* item  = (const float*)d_in[0];
    const float* user  = (const float*)d_in[1];
    const float* W_ih  = (const float*)d_in[2];
    const float* W_hh  = (const float*)d_in[3];
    const float* b_ih  = (const float*)d_in[4];
    const float* b_hh  = (const float*)d_in[5];
    const float* W_out = (const float*)d_in[6];
    const float* b_out = (const float*)d_in[7];
    float* out = (float*)d_out;

    prep_weights<<<(2 * 8 * 48 * 32 + 255) / 256, 256>>>(W_ih, W_hh);

    size_t smem = (size_t)(3 * TN * SMP) * sizeof(unsigned short)  // x + h(hi,lo)
                + 8 * TN * sizeof(float)        // outb
                + 512 * sizeof(float);          // biases
    // 26112 + 1024 + 2048 = 29184 B per CTA -> 58368 B per SM at 2 CTAs
    cudaFuncSetAttribute(gru_mma,
                         cudaFuncAttributeMaxDynamicSharedMemorySize, (int)smem);
    gru_mma<<<NCTA, NTHR, smem>>>(item, user, b_ih, b_hh, W_out, b_out, out);
}